// round 4
// baseline (speedup 1.0000x reference)
#include <cuda_runtime.h>
#include <cuda_bf16.h>
#include <math.h>

// Problem constants (fixed bench shapes)
#define BH    32            // B*H = 4*8
#define LSEQ  2048          // sequence length
#define DIM   64            // head dim
#define USEL  40            // u = U_part = 5*ceil(ln(2048)) = 40
#define NCH   16            // key chunks for split-softmax attention
#define CHK   (LSEQ/NCH)    // 128 keys per chunk
#define KVS   68            // KV smem row stride (16B aligned, phase-conflict-free)
#define QSPLIT 4            // q-range splits for m_kernel (32*4=128 blocks, 1/SM)

// -------- scratch (device globals; no allocation allowed) --------
__device__ unsigned g_Mkey[BH * LSEQ];              // monotone-mapped sparsity keys
__device__ int   g_topk[BH * USEL];                 // selected query indices
__device__ float g_meanV[BH * DIM];                 // per-(b,h) mean of V
__device__ float g_pm[BH * NCH * USEL];             // partial softmax max
__device__ float g_pl[BH * NCH * USEL];             // partial softmax denom
__device__ float g_pacc[(size_t)BH * NCH * USEL * DIM]; // partial outputs (5.2 MB)

__device__ __forceinline__ unsigned f2key(float x) {
    unsigned k = __float_as_uint(x);
    return (k & 0x80000000u) ? ~k : (k | 0x80000000u);
}

// ================= 1. mean of V per (b,h) =================
__global__ void mean_kernel(const float* __restrict__ V) {
    __shared__ float sb[256];
    int bh = blockIdx.x, t = threadIdx.x;
    int d = t & 63, part = t >> 6;
    const float* Vb = V + (size_t)bh * LSEQ * DIM;
    float s = 0.f;
    for (int l = part; l < LSEQ; l += 4)
        s += Vb[(size_t)l * DIM + d];
    sb[t] = s;
    __syncthreads();
    if (t < 64)
        g_meanV[bh * DIM + t] =
            (sb[t] + sb[t + 64] + sb[t + 128] + sb[t + 192]) * (1.0f / LSEQ);
}

// ================= 2. broadcast-fill output with meanV =================
__global__ void fill_kernel(float4* __restrict__ out) {
    int i = blockIdx.x * blockDim.x + threadIdx.x;   // over BH*LSEQ*16 float4s
    int bh = i >> 15;                                // LSEQ*16 = 32768
    int d4 = i & 15;
    out[i] = ((const float4*)g_meanV)[bh * 16 + d4];
}

// ================= 3. M scores (sampled QK gather) =================
// One block (1024 threads) per (bh, quarter of queries) -> <=1 block per SM,
// so each SM's L1D caches key rows of a SINGLE bh (512 KB working set).
// Warp layout: 4 groups of 8 lanes; group g handles samples {s0+g, s0+4+g}
// (8 samples in flight per warp). Lane h reads float4 #h and #(h+8) of the
// key row -> each warp LDG.128 covers 4 FULL 128B lines (fully coalesced).
__global__ __launch_bounds__(1024) void m_kernel(const float* __restrict__ Q,
                                                 const float* __restrict__ K,
                                                 const int* __restrict__ idxs, int u) {
    int t = threadIdx.x, lane = t & 31, warp = t >> 5;
    int bh = blockIdx.y;
    int qlo = (LSEQ * blockIdx.x) / QSPLIT;
    int qhi = (LSEQ * (blockIdx.x + 1)) / QSPLIT;
    int g = lane >> 3, h = lane & 7;

    const float* Kb = K + (size_t)bh * LSEQ * DIM;

    for (int q = qlo + warp; q < qhi; q += 32) {
        const float4* Q4 = (const float4*)(Q + ((size_t)bh * LSEQ + q) * DIM);
        float4 qa = __ldg(Q4 + h);
        float4 qb = __ldg(Q4 + h + 8);

        const int* ip = idxs + (size_t)q * u;
        int r0 = __ldg(ip + min(lane, u - 1));
        int r1 = (u > 32) ? __ldg(ip + min(lane + 32, u - 1)) : 0;

        float mx = -1e30f, sm = 0.f;
        for (int s0 = 0; s0 < u; s0 += 8) {
            int sA = s0 + g, sB = s0 + 4 + g;
            int kiA = (sA < 32) ? __shfl_sync(0xFFFFFFFFu, r0, sA)
                                : __shfl_sync(0xFFFFFFFFu, r1, sA & 31);
            int kiB = (sB < 32) ? __shfl_sync(0xFFFFFFFFu, r0, sB)
                                : __shfl_sync(0xFFFFFFFFu, r1, sB & 31);
            const float4* KA = (const float4*)(Kb + (size_t)kiA * DIM);
            const float4* KB = (const float4*)(Kb + (size_t)kiB * DIM);
            float4 a0 = __ldg(KA + h), a1 = __ldg(KA + h + 8);
            float4 b0 = __ldg(KB + h), b1 = __ldg(KB + h + 8);

            float dA = qa.x * a0.x;
            dA = fmaf(qa.y, a0.y, dA);
            dA = fmaf(qa.z, a0.z, dA);
            dA = fmaf(qa.w, a0.w, dA);
            dA = fmaf(qb.x, a1.x, dA);
            dA = fmaf(qb.y, a1.y, dA);
            dA = fmaf(qb.z, a1.z, dA);
            dA = fmaf(qb.w, a1.w, dA);

            float dB = qa.x * b0.x;
            dB = fmaf(qa.y, b0.y, dB);
            dB = fmaf(qa.z, b0.z, dB);
            dB = fmaf(qa.w, b0.w, dB);
            dB = fmaf(qb.x, b1.x, dB);
            dB = fmaf(qb.y, b1.y, dB);
            dB = fmaf(qb.z, b1.z, dB);
            dB = fmaf(qb.w, b1.w, dB);

            dA += __shfl_xor_sync(0xFFFFFFFFu, dA, 1);
            dA += __shfl_xor_sync(0xFFFFFFFFu, dA, 2);
            dA += __shfl_xor_sync(0xFFFFFFFFu, dA, 4);
            dB += __shfl_xor_sync(0xFFFFFFFFu, dB, 1);
            dB += __shfl_xor_sync(0xFFFFFFFFu, dB, 2);
            dB += __shfl_xor_sync(0xFFFFFFFFu, dB, 4);

            if (sA < u) { mx = fmaxf(mx, dA); sm += dA; }
            if (sB < u) { mx = fmaxf(mx, dB); sm += dB; }
        }
        // fold the 4 groups
        mx = fmaxf(mx, __shfl_xor_sync(0xFFFFFFFFu, mx, 8));
        mx = fmaxf(mx, __shfl_xor_sync(0xFFFFFFFFu, mx, 16));
        sm += __shfl_xor_sync(0xFFFFFFFFu, sm, 8);
        sm += __shfl_xor_sync(0xFFFFFFFFu, sm, 16);
        if (lane == 0)
            g_Mkey[bh * LSEQ + q] = f2key(mx - sm * (1.0f / LSEQ));
    }
}

// ================= 4. top-40 per (b,h) via radix select =================
// 4x 8-bit histogram passes; warp 0 does the suffix scan in registers.
__global__ __launch_bounds__(256) void topk_kernel() {
    __shared__ unsigned skeys[LSEQ];        // 8 KB
    __shared__ unsigned hist[256];
    __shared__ int ebuf[64];
    __shared__ unsigned s_prefix;
    __shared__ int s_remaining, s_cnt, s_eq;

    int bh = blockIdx.x, t = threadIdx.x;
    for (int i = t; i < LSEQ; i += 256)
        skeys[i] = g_Mkey[bh * LSEQ + i];
    if (t == 0) { s_prefix = 0u; s_remaining = USEL; s_cnt = 0; s_eq = 0; }
    __syncthreads();

    const unsigned himask[4] = {0u, 0xFF000000u, 0xFFFF0000u, 0xFFFFFF00u};
#pragma unroll
    for (int r = 0; r < 4; r++) {
        int shift = 24 - 8 * r;
        hist[t] = 0;
        __syncthreads();
        unsigned pfx = s_prefix;
        for (int i = t; i < LSEQ; i += 256) {
            unsigned k = skeys[i];
            if ((k & himask[r]) == pfx)
                atomicAdd(&hist[(k >> shift) & 255u], 1u);
        }
        __syncthreads();
        if (t < 32) {
            unsigned v[8], tot = 0;
#pragma unroll
            for (int c = 0; c < 8; c++) { v[c] = hist[t * 8 + c]; tot += v[c]; }
            unsigned suf = tot;
#pragma unroll
            for (int off = 1; off < 32; off <<= 1) {
                unsigned o = __shfl_down_sync(0xFFFFFFFFu, suf, off);
                if (t + off < 32) suf += o;
            }
            unsigned below = suf - tot;    // suffix starting at next lane's bins
            int rem = s_remaining;         // all lanes read BEFORE any write
#pragma unroll
            for (int c = 7; c >= 0; c--) {
                unsigned here = below + v[c];
                if ((int)here >= rem && (int)below < rem) {   // exactly one (lane,c)
                    s_prefix = pfx | ((unsigned)(t * 8 + c) << shift);
                    s_remaining = rem - (int)below;
                }
                below = here;
            }
        }
        __syncthreads();
    }

    unsigned T = s_prefix;          // exact key of the 40th-largest value
    int need_eq = s_remaining;      // how many == T to take

    for (int i = t; i < LSEQ; i += 256) {
        unsigned k = skeys[i];
        if (k > T) {
            int p = atomicAdd(&s_cnt, 1);
            g_topk[bh * USEL + p] = i;
        } else if (k == T) {
            int p = atomicAdd(&s_eq, 1);
            if (p < 64) ebuf[p] = i;
        }
    }
    __syncthreads();

    int cnt_gt = s_cnt, cnt_eq = s_eq;
    if (cnt_eq == need_eq) {
        if (t < cnt_eq)
            g_topk[bh * USEL + cnt_gt + t] = ebuf[t];
    } else if (t == 0) {
        if (cnt_eq <= 64) {
            for (int n = 0; n < need_eq; n++) {
                int bi = -1, bv = LSEQ;
                for (int j = 0; j < cnt_eq; j++)
                    if (ebuf[j] < bv) { bv = ebuf[j]; bi = j; }
                g_topk[bh * USEL + cnt_gt + n] = bv;
                ebuf[bi] = LSEQ;
            }
        } else {
            int n = 0;
            for (int i = 0; i < LSEQ && n < need_eq; i++)
                if (skeys[i] == T) g_topk[bh * USEL + cnt_gt + n++] = i;
        }
    }
}

// ================= 5. attention partials: block = (key-chunk, bh) =================
__global__ __launch_bounds__(256) void attn_kernel(const float* __restrict__ Q,
                                                   const float* __restrict__ K,
                                                   const float* __restrict__ V) {
    __shared__ float Qs[USEL * DIM];     // 10.0 KB (pre-scaled Q)
    __shared__ float KV[64 * KVS];       // 17.0 KB (K tile, then V tile)
    __shared__ float Pt[USEL * 64];      // 10.0 KB (scores -> probs)
    __shared__ float s_m[USEL], s_l[USEL], s_f[USEL], s_tm[USEL];

    int ch = blockIdx.x, bh = blockIdx.y;
    int t = threadIdx.x;
    int i = t >> 5, j = t & 31;

    const float* Kb = K + (size_t)bh * LSEQ * DIM;
    const float* Vb = V + (size_t)bh * LSEQ * DIM;

    for (int e = t; e < USEL * DIM; e += 256) {
        int q = e >> 6, d = e & 63;
        int qi = g_topk[bh * USEL + q];
        Qs[e] = Q[((size_t)bh * LSEQ + qi) * DIM + d] * 0.125f;
    }
    if (t < USEL) { s_m[t] = -1e30f; s_l[t] = 0.f; }
    float acc[5][2];
#pragma unroll
    for (int a = 0; a < 5; a++) { acc[a][0] = 0.f; acc[a][1] = 0.f; }
    __syncthreads();

    int kbase0 = ch * CHK;
    for (int kt = 0; kt < CHK / 64; kt++) {
        int kb = kbase0 + kt * 64;

        // --- stage K tile: 1024 float4s, vectorized ---
#pragma unroll
        for (int rr = 0; rr < 4; rr++) {
            int f = t + rr * 256;
            int r = f >> 4, c4 = f & 15;
            float4 v = __ldg((const float4*)(Kb + (size_t)(kb + r) * DIM) + c4);
            *(float4*)&KV[r * KVS + c4 * 4] = v;
        }
        __syncthreads();

        // --- S = Qs @ K^T ---
        float s[5][2];
#pragma unroll
        for (int a = 0; a < 5; a++) { s[a][0] = 0.f; s[a][1] = 0.f; }
#pragma unroll
        for (int d4 = 0; d4 < 16; d4++) {
            float4 k0 = *(const float4*)&KV[j * KVS + d4 * 4];
            float4 k1 = *(const float4*)&KV[(j + 32) * KVS + d4 * 4];
#pragma unroll
            for (int a = 0; a < 5; a++) {
                float4 qv = *(const float4*)&Qs[(i + 8 * a) * 64 + d4 * 4];
                float t0 = s[a][0];
                t0 = fmaf(qv.x, k0.x, t0);
                t0 = fmaf(qv.y, k0.y, t0);
                t0 = fmaf(qv.z, k0.z, t0);
                t0 = fmaf(qv.w, k0.w, t0);
                s[a][0] = t0;
                float t1 = s[a][1];
                t1 = fmaf(qv.x, k1.x, t1);
                t1 = fmaf(qv.y, k1.y, t1);
                t1 = fmaf(qv.z, k1.z, t1);
                t1 = fmaf(qv.w, k1.w, t1);
                s[a][1] = t1;
            }
        }
#pragma unroll
        for (int a = 0; a < 5; a++) {
            Pt[(i + 8 * a) * 64 + j]      = s[a][0];
            Pt[(i + 8 * a) * 64 + j + 32] = s[a][1];
        }
        __syncthreads();

        // tile max + rescale factor
        if (t < USEL) {
            float tm = -1e30f;
            for (int k = 0; k < 64; k++) tm = fmaxf(tm, Pt[t * 64 + k]);
            float mo = s_m[t];
            float mn = fmaxf(mo, tm);
            s_tm[t] = mn;
            s_f[t]  = __expf(mo - mn);
            s_m[t]  = mn;
        }
        __syncthreads();

        // stage V over K buffer
#pragma unroll
        for (int rr = 0; rr < 4; rr++) {
            int f = t + rr * 256;
            int r = f >> 4, c4 = f & 15;
            float4 v = __ldg((const float4*)(Vb + (size_t)(kb + r) * DIM) + c4);
            *(float4*)&KV[r * KVS + c4 * 4] = v;
        }

        // exponentiate scores; rescale accumulators
        for (int e = t; e < USEL * 64; e += 256) {
            int q = e >> 6;
            Pt[e] = __expf(Pt[e] - s_tm[q]);
        }
#pragma unroll
        for (int a = 0; a < 5; a++) {
            float f = s_f[i + 8 * a];
            acc[a][0] *= f;
            acc[a][1] *= f;
        }
        __syncthreads();

        if (t < USEL) {
            float su = 0.f;
            for (int k = 0; k < 64; k++) su += Pt[t * 64 + k];
            s_l[t] = s_l[t] * s_f[t] + su;
        }

        // --- acc += P @ V ---
#pragma unroll
        for (int k4 = 0; k4 < 16; k4++) {
            int k = k4 * 4;
            float v00 = KV[(k + 0) * KVS + j];
            float v01 = KV[(k + 1) * KVS + j];
            float v02 = KV[(k + 2) * KVS + j];
            float v03 = KV[(k + 3) * KVS + j];
            float v10 = KV[(k + 0) * KVS + j + 32];
            float v11 = KV[(k + 1) * KVS + j + 32];
            float v12 = KV[(k + 2) * KVS + j + 32];
            float v13 = KV[(k + 3) * KVS + j + 32];
#pragma unroll
            for (int a = 0; a < 5; a++) {
                float4 p = *(const float4*)&Pt[(i + 8 * a) * 64 + k];
                float t0 = acc[a][0];
                t0 = fmaf(p.x, v00, t0);
                t0 = fmaf(p.y, v01, t0);
                t0 = fmaf(p.z, v02, t0);
                t0 = fmaf(p.w, v03, t0);
                acc[a][0] = t0;
                float t1 = acc[a][1];
                t1 = fmaf(p.x, v10, t1);
                t1 = fmaf(p.y, v11, t1);
                t1 = fmaf(p.z, v12, t1);
                t1 = fmaf(p.w, v13, t1);
                acc[a][1] = t1;
            }
        }
        __syncthreads();
    }

    float* pa = g_pacc + (size_t)(bh * NCH + ch) * USEL * DIM;
#pragma unroll
    for (int a = 0; a < 5; a++) {
        int q = i + 8 * a;
        pa[q * DIM + j]      = acc[a][0];
        pa[q * DIM + j + 32] = acc[a][1];
    }
    if (t < USEL) {
        g_pm[(bh * NCH + ch) * USEL + t] = s_m[t];
        g_pl[(bh * NCH + ch) * USEL + t] = s_l[t];
    }
}

// ================= 6. merge partials, scatter into output =================
__global__ void merge_kernel(float* __restrict__ out) {
    int u = blockIdx.x, bh = blockIdx.y, d = threadIdx.x;
    float M = -1e30f;
#pragma unroll
    for (int c = 0; c < NCH; c++)
        M = fmaxf(M, g_pm[(bh * NCH + c) * USEL + u]);
    float L = 0.f, o = 0.f;
#pragma unroll
    for (int c = 0; c < NCH; c++) {
        float w = __expf(g_pm[(bh * NCH + c) * USEL + u] - M);
        L += g_pl[(bh * NCH + c) * USEL + u] * w;
        o = fmaf(g_pacc[((size_t)(bh * NCH + c) * USEL + u) * DIM + d], w, o);
    }
    int qi = g_topk[bh * USEL + u];
    out[((size_t)bh * LSEQ + qi) * DIM + d] = o / L;
}

// ================= launcher =================
extern "C" void kernel_launch(void* const* d_in, const int* in_sizes, int n_in,
                              void* d_out, int out_size) {
    const float* Q    = (const float*)d_in[0];
    const float* K    = (const float*)d_in[1];
    const float* V    = (const float*)d_in[2];
    const int*   idxs = (const int*)d_in[3];
    float* out = (float*)d_out;
    int u = in_sizes[3] / LSEQ;   // 40

    mean_kernel<<<BH, 256>>>(V);
    fill_kernel<<<(BH * LSEQ * 16) / 256, 256>>>((float4*)out);
    m_kernel<<<dim3(QSPLIT, BH), 1024>>>(Q, K, idxs, u);
    topk_kernel<<<BH, 256>>>();
    attn_kernel<<<dim3(NCH, BH), 256>>>(Q, K, V);
    merge_kernel<<<dim3(USEL, BH), 64>>>(out);
}